// round 15
// baseline (speedup 1.0000x reference)
#include <cuda_runtime.h>

#define BS     4096
#define SEGLEN 8192
#define LAM1   8e-05f
#define LAM2   8e-05f
#define TPB    256
#define NWARP  (TPB / 32)

// Scratch (allocation-free rule: __device__ globals).
// g_hist/g_ticket are zero at load; epilogue re-zeros them (replay-safe).
__device__ float        g_base[BS];     // LAM1*smooth + LAM2*spars per row
__device__ int          g_ms[BS];       // argmax index per row
__device__ int          g_hist[SEGLEN]; // histogram -> T in place -> re-zeroed
__device__ unsigned int g_ticket;

// ---------------------------------------------------------------------------
// Single fused kernel.
// Phase 1 (all 4096 blocks): row stats + histogram atomic. Publication via
// atom.add.RELEASE.gpu (store drain only -- NO L1 invalidation; the acq_rel
// variant in R14 flushed L1 on every block and cost ~4 us).
// Phase 2 (last block only): ONE fence.acq_rel.gpu (single L1 invalidation),
// fused suffix scan on g_hist in place, gather, deterministic reduction,
// self-clean.
// ---------------------------------------------------------------------------
__global__ __launch_bounds__(TPB, 6) void fused(const float* __restrict__ scores,
                                                const int*   __restrict__ labels,
                                                float*       __restrict__ out) {
    __shared__ float ssum[NWARP], ssq[NWARP], smax[NWARP];
    __shared__ int   sidx[NWARP];
    __shared__ int   wt0[NWARP], wt1[NWARP], wo0[NWARP], wo1[NWARP];
    __shared__ float red[NWARP];
    __shared__ int   s_last;

    const int row = blockIdx.x;
    const float*  rf = scores + (size_t)row * SEGLEN;
    const float4* rp = (const float4*)rf;
    const int t = threadIdx.x, lane = t & 31, w = t >> 5;

    // ---- phase 1: row stats (measured-best interleaved layout) ----------
    float sum = 0.f, sq = 0.f, maxv = -1.f;
    int maxq = 0;

#pragma unroll
    for (int g = 0; g < 8; g++) {
        const int v4 = g * TPB + t;     // coalesced across lanes
        const int e  = v4 * 4;
        float4 x = rp[v4];
        float nxt = (e + 4 < SEGLEN) ? __ldg(rf + e + 4) : x.w;  // last: diff 0

        sum += (x.x + x.y) + (x.z + x.w);
        float d0 = x.y - x.x, d1 = x.z - x.y, d2 = x.w - x.z, d3 = nxt - x.w;
        sq += d0 * d0 + d1 * d1 + d2 * d2 + d3 * d3;

        float m4 = fmaxf(fmaxf(x.x, x.y), fmaxf(x.z, x.w));
        if (m4 > maxv) { maxv = m4; maxq = v4; }  // strict > keeps earliest v4
    }

#pragma unroll
    for (int off = 16; off > 0; off >>= 1) {
        sum += __shfl_down_sync(0xFFFFFFFFu, sum, off);
        sq  += __shfl_down_sync(0xFFFFFFFFu, sq,  off);
        float ov = __shfl_down_sync(0xFFFFFFFFu, maxv, off);
        int   oq = __shfl_down_sync(0xFFFFFFFFu, maxq, off);
        if (ov > maxv || (ov == maxv && oq < maxq)) { maxv = ov; maxq = oq; }
    }
    if (lane == 0) { ssum[w] = sum; ssq[w] = sq; smax[w] = maxv; sidx[w] = maxq; }
    __syncthreads();

    if (t == 0) {
        float S = 0.f, Q = 0.f, M = -1.f;
        int Qi = 0;
#pragma unroll
        for (int i = 0; i < NWARP; i++) {
            S += ssum[i];
            Q += ssq[i];
            if (smax[i] > M || (smax[i] == M && sidx[i] < Qi)) { M = smax[i]; Qi = sidx[i]; }
        }
        float4 xx = rp[Qi];
        int e = Qi * 4;
        int idx = (xx.x == M) ? e : (xx.y == M) ? e + 1 : (xx.z == M) ? e + 2 : e + 3;
        g_base[row] = LAM1 * Q + LAM2 * S;
        g_ms[row]   = idx;
        if (labels[row] == 0) atomicAdd(&g_hist[idx], 1);  // relaxed ATOMG

        // RELEASE-only ticket: orders this block's writes, no L1 flush
        unsigned int old;
        asm volatile("atom.add.release.gpu.u32 %0, [%1], %2;"
                     : "=r"(old) : "l"(&g_ticket), "r"(1u) : "memory");
        s_last = (old == (unsigned int)(BS - 1));
    }
    __syncthreads();
    if (!s_last) return;

    // ---- phase 2: last block epilogue ------------------------------------
    // One acquire fence (single L1 invalidation, one SM) imports all blocks'
    // published writes via the release sequence on g_ticket.
    asm volatile("fence.acq_rel.gpu;" ::: "memory");

    // Thread t owns bins [32t, 32t+32) as int4 slots [8t, 8t+8).
    int4* hp = (int4*)g_hist;
    int4 hv[8];
#pragma unroll
    for (int g = 0; g < 8; g++) hv[g] = hp[t * 8 + g];

    const int binbase = t * 32;
    int c0 = 0, c1 = 0;
#pragma unroll
    for (int g = 0; g < 8; g++) {
        const int b = binbase + g * 4;
        c0 += (hv[g].x + hv[g].y) + (hv[g].z + hv[g].w);
        c1 += hv[g].x * (b + 1) + hv[g].y * (b + 2) + hv[g].z * (b + 3) + hv[g].w * (b + 4);
    }

    // warp inclusive suffix scan of (c0, c1)
    int i0 = c0, i1 = c1;
#pragma unroll
    for (int off = 1; off < 32; off <<= 1) {
        int v0 = __shfl_down_sync(0xFFFFFFFFu, i0, off);
        int v1 = __shfl_down_sync(0xFFFFFFFFu, i1, off);
        if (lane + off < 32) { i0 += v0; i1 += v1; }
    }
    if (lane == 0) { wt0[w] = i0; wt1[w] = i1; }
    __syncthreads();

    // warp 0 (lanes 0..NWARP-1): exclusive suffix over NWARP warp totals
    if (w == 0 && lane < NWARP) {
        int s0 = 0, s1 = 0;
#pragma unroll
        for (int i = 0; i < NWARP; i++)
            if (i > lane) { s0 += wt0[i]; s1 += wt1[i]; }
        wo0[lane] = s0;
        wo1[lane] = s1;
    }
    __syncthreads();

    // serial descending within chunk: T[m] = S1[m] - m*S0[m], stored in place
    int r0 = (i0 - c0) + wo0[w];
    int r1 = (i1 - c1) + wo1[w];
#pragma unroll
    for (int g = 7; g >= 0; g--) {
        const int b = binbase + g * 4;
        int4 h = hv[g];
        int t3_0 = r0 + h.w,        t3_1 = r1 + h.w * (b + 4);
        int t2_0 = t3_0 + h.z,      t2_1 = t3_1 + h.z * (b + 3);
        int t1_0 = t2_0 + h.y,      t1_1 = t2_1 + h.y * (b + 2);
        int t0_0 = t1_0 + h.x,      t0_1 = t1_1 + h.x * (b + 1);
        hp[t * 8 + g] = make_int4(t0_1 - b * t0_0,
                                  t1_1 - (b + 1) * t1_0,
                                  t2_1 - (b + 2) * t2_0,
                                  t3_1 - (b + 3) * t3_0);
        r0 = t0_0;
        r1 = t0_1;
    }
    __syncthreads();  // T visible block-wide before gather

    // gather per-positive-row loss (16 rows per thread), fixed order
    float acc = 0.f;
#pragma unroll
    for (int it = 0; it < BS / TPB; it++) {
        int i = it * TPB + t;
        if (labels[i] == 1)
            acc += g_base[i] + (float)g_hist[g_ms[i]];
    }
    __syncthreads();  // all gathers done before zeroing

    // self-clean for next graph replay
#pragma unroll
    for (int g = 0; g < 8; g++) hp[t * 8 + g] = make_int4(0, 0, 0, 0);

    // deterministic reduction
#pragma unroll
    for (int off = 16; off > 0; off >>= 1)
        acc += __shfl_down_sync(0xFFFFFFFFu, acc, off);
    if (lane == 0) red[w] = acc;
    __syncthreads();
    if (t == 0) {
        float v = 0.f;
#pragma unroll
        for (int i = 0; i < NWARP; i++) v += red[i];
        out[0] = v / (float)BS;
        g_ticket = 0;  // reset for next replay
    }
}

extern "C" void kernel_launch(void* const* d_in, const int* in_sizes, int n_in,
                              void* d_out, int out_size) {
    const float* scores = (const float*)d_in[0];
    const int*   labels = (const int*)d_in[1];
    float*       out    = (float*)d_out;

    fused<<<BS, TPB>>>(scores, labels, out);
}

// round 16
// speedup vs baseline: 1.1476x; 1.1476x over previous
#include <cuda_runtime.h>

#define BS     4096
#define SEGLEN 8192
#define LAM1   8e-05f
#define LAM2   8e-05f
#define TPB    256
#define NWARP  (TPB / 32)

// Scratch (allocation-free rule: __device__ globals).
// g_hist is zero at load; finalize re-zeros it after use (replay-safe).
__device__ float g_base[BS];     // LAM1*smooth + LAM2*spars per row
__device__ int   g_ms[BS];       // argmax index per row
__device__ int   g_hist[SEGLEN]; // histogram of ms over negative rows

// ---------------------------------------------------------------------------
// Kernel 1: per-row stats (R1 structure — fastest measured: 22.6us).
// Interleaved coalesced float4 loads, boundary scalar __ldg (L1 hit),
// EXACT elementwise argmax (no tail reload). Labels prefetched at start.
// ---------------------------------------------------------------------------
__global__ __launch_bounds__(TPB) void row_stats(const float* __restrict__ scores,
                                                 const int*   __restrict__ labels) {
    const int row = blockIdx.x;
    const float*  rf = scores + (size_t)row * SEGLEN;
    const float4* rp = (const float4*)rf;
    const int t = threadIdx.x, lane = t & 31, w = t >> 5;

    // prefetch label early; result consumed only in thread 0's tail
    int lb = 0;
    if (t == 0) lb = labels[row];

    float sum = 0.f, sq = 0.f, maxv = -1.f;
    int maxi = 0;

#pragma unroll
    for (int g = 0; g < 8; g++) {
        const int v4 = g * TPB + t;     // coalesced across lanes
        const int e  = v4 * 4;
        float4 x = rp[v4];
        float nxt = (e + 4 < SEGLEN) ? __ldg(rf + e + 4) : x.w;  // last: diff 0

        sum += (x.x + x.y) + (x.z + x.w);
        float d0 = x.y - x.x, d1 = x.z - x.y, d2 = x.w - x.z, d3 = nxt - x.w;
        sq += d0 * d0 + d1 * d1 + d2 * d2 + d3 * d3;

        // strict > preserves first occurrence (indices ascend within thread)
        if (x.x > maxv) { maxv = x.x; maxi = e;     }
        if (x.y > maxv) { maxv = x.y; maxi = e + 1; }
        if (x.z > maxv) { maxv = x.z; maxi = e + 2; }
        if (x.w > maxv) { maxv = x.w; maxi = e + 3; }
    }

    // warp reduce (fixed order -> deterministic); tie -> min element index
#pragma unroll
    for (int off = 16; off > 0; off >>= 1) {
        sum += __shfl_down_sync(0xFFFFFFFFu, sum, off);
        sq  += __shfl_down_sync(0xFFFFFFFFu, sq,  off);
        float ov = __shfl_down_sync(0xFFFFFFFFu, maxv, off);
        int   oi = __shfl_down_sync(0xFFFFFFFFu, maxi, off);
        if (ov > maxv || (ov == maxv && oi < maxi)) { maxv = ov; maxi = oi; }
    }

    __shared__ float ssum[NWARP], ssq[NWARP], smax[NWARP];
    __shared__ int   sidx[NWARP];
    if (lane == 0) { ssum[w] = sum; ssq[w] = sq; smax[w] = maxv; sidx[w] = maxi; }
    __syncthreads();

    if (t == 0) {
        float S = 0.f, Q = 0.f, M = -1.f;
        int I = 0;
#pragma unroll
        for (int i = 0; i < NWARP; i++) {
            S += ssum[i];
            Q += ssq[i];
            if (smax[i] > M || (smax[i] == M && sidx[i] < I)) { M = smax[i]; I = sidx[i]; }
        }
        g_base[row] = LAM1 * Q + LAM2 * S;
        g_ms[row]   = I;
        if (lb == 0) atomicAdd(&g_hist[I], 1);  // int -> deterministic
    }
    __syncthreads();
    cudaTriggerProgrammaticLaunchCompletion();
}

// ---------------------------------------------------------------------------
// Kernel 2 (single block, 1024 threads, PDL):
//   T[m] = S1[m] - m*S0[m] via one fused suffix scan of (S0, S1).
//   Gather margin = T[ms[i]] for positive rows + deterministic reduction.
//   Self-cleans g_hist for the next graph replay.
// ---------------------------------------------------------------------------
__global__ __launch_bounds__(1024) void finalize(const int* __restrict__ labels,
                                                 float* __restrict__ out) {
    __shared__ int   Tm[SEGLEN];    // T[m]
    __shared__ int   wt0[32], wt1[32], wo0[32], wo1[32];
    __shared__ float red[32];

    const int t = threadIdx.x;
    const int lane = t & 31, w = t >> 5;
    const int base = t * 8;         // this thread owns bins [8t, 8t+8)

    // ---- prologue: independent of row_stats ----
    int4 lb = ((const int4*)labels)[t];   // rows 4t..4t+3
    // ---- wait for row_stats results ----
    cudaGridDependencySynchronize();

    // load this thread's 8 hist bins (coalesced int4, L2-hot)
    int4 h0 = ((const int4*)g_hist)[2 * t];
    int4 h1 = ((const int4*)g_hist)[2 * t + 1];
    int4   ms = ((const int4*)g_ms)[t];
    float4 gb = ((const float4*)g_base)[t];

    int hreg[8] = {h0.x, h0.y, h0.z, h0.w, h1.x, h1.y, h1.z, h1.w};

    // chunk totals: c0 = sum h, c1 = sum h*(bin+1)
    int c0 = 0, c1 = 0;
#pragma unroll
    for (int k = 0; k < 8; k++) { c0 += hreg[k]; c1 += hreg[k] * (base + k + 1); }

    // warp inclusive suffix scan of (c0, c1)
    int i0 = c0, i1 = c1;
#pragma unroll
    for (int off = 1; off < 32; off <<= 1) {
        int v0 = __shfl_down_sync(0xFFFFFFFFu, i0, off);
        int v1 = __shfl_down_sync(0xFFFFFFFFu, i1, off);
        if (lane + off < 32) { i0 += v0; i1 += v1; }
    }
    if (lane == 0) { wt0[w] = i0; wt1[w] = i1; }
    __syncthreads();

    // warp 0: exclusive suffix over 32 warp totals (both components)
    if (w == 0) {
        int v0 = wt0[lane], v1 = wt1[lane];
        int s0 = v0, s1 = v1;
#pragma unroll
        for (int off = 1; off < 32; off <<= 1) {
            int u0 = __shfl_down_sync(0xFFFFFFFFu, s0, off);
            int u1 = __shfl_down_sync(0xFFFFFFFFu, s1, off);
            if (lane + off < 32) { s0 += u0; s1 += u1; }
        }
        wo0[lane] = s0 - v0;  // sum of warps strictly after lane
        wo1[lane] = s1 - v1;
    }
    __syncthreads();

    // serial descending within chunk: inclusive suffixes r0, r1; write T
    int r0 = (i0 - c0) + wo0[w];
    int r1 = (i1 - c1) + wo1[w];
#pragma unroll
    for (int k = 7; k >= 0; k--) {
        const int bin = base + k;
        r0 += hreg[k];
        r1 += hreg[k] * (bin + 1);
        Tm[bin] = r1 - bin * r0;
    }
    __syncthreads();

    // per-positive-row loss (this thread's 4 rows), fixed order
    float acc = 0.f;
    if (lb.x == 1) acc += gb.x + (float)Tm[ms.x];
    if (lb.y == 1) acc += gb.y + (float)Tm[ms.y];
    if (lb.z == 1) acc += gb.z + (float)Tm[ms.z];
    if (lb.w == 1) acc += gb.w + (float)Tm[ms.w];

    // self-clean histogram for the next graph replay
    ((int4*)g_hist)[2 * t]     = make_int4(0, 0, 0, 0);
    ((int4*)g_hist)[2 * t + 1] = make_int4(0, 0, 0, 0);

    // deterministic tree reduction
#pragma unroll
    for (int off = 16; off > 0; off >>= 1)
        acc += __shfl_down_sync(0xFFFFFFFFu, acc, off);
    if (lane == 0) red[w] = acc;
    __syncthreads();
    if (w == 0) {
        float v = red[lane];
#pragma unroll
        for (int off = 16; off > 0; off >>= 1)
            v += __shfl_down_sync(0xFFFFFFFFu, v, off);
        if (lane == 0) out[0] = v / (float)BS;
    }
}

extern "C" void kernel_launch(void* const* d_in, const int* in_sizes, int n_in,
                              void* d_out, int out_size) {
    const float* scores = (const float*)d_in[0];
    const int*   labels = (const int*)d_in[1];
    float*       out    = (float*)d_out;

    row_stats<<<BS, TPB>>>(scores, labels);

    // finalize with Programmatic Dependent Launch
    cudaLaunchConfig_t cfg = {};
    cfg.gridDim  = dim3(1, 1, 1);
    cfg.blockDim = dim3(1024, 1, 1);
    cfg.dynamicSmemBytes = 0;
    cudaLaunchAttribute attrs[1];
    attrs[0].id = cudaLaunchAttributeProgrammaticStreamSerialization;
    attrs[0].val.programmaticStreamSerializationAllowed = 1;
    cfg.attrs = attrs;
    cfg.numAttrs = 1;
    cudaLaunchKernelEx(&cfg, finalize, labels, out);
}